// round 1
// baseline (speedup 1.0000x reference)
#include <cuda_runtime.h>

#define NB   32
#define CC   49
#define HW   81
#define PITCH 84          // padded row (multiple of 4), pads zeroed
#define Q4   21           // PITCH/4
#define OO   24
#define KK   7
#define DTOT 49

// scratch: per-(n,o) contribution tile [CC x PITCH], 768*4116 floats ~= 12.6MB
__device__ float g_scr[(size_t)NB * OO * CC * PITCH];

__global__ __launch_bounds__(128) void k_main(const float* __restrict__ x,
                                              const float* __restrict__ w) {
    const int n = blockIdx.x / OO;
    const int o = blockIdx.x % OO;
    __shared__ float xs[CC * PITCH];
    __shared__ float ms[DTOT * PITCH];
    __shared__ float gs[CC * DTOT];
    const int tid = threadIdx.x;

    // ---- load x[n] into smem (pitch 84), zero pads ----
    const float* xn = x + (size_t)n * CC * HW;
    for (int i = tid; i < CC * HW; i += 128) {
        int c = i / HW, hw = i - c * HW;
        xs[c * PITCH + hw] = xn[i];
    }
    for (int i = tid; i < CC * 3; i += 128) {
        int c = i / 3;
        xs[c * PITCH + HW + (i - c * 3)] = 0.f;
    }
    float wl[KK];
#pragma unroll
    for (int k = 0; k < KK; k++) wl[k] = w[o * KK + k];
    __syncthreads();

    // ---- depth conv along d (bias omitted: cancels in softmax) ----
    for (int i = tid; i < DTOT * HW; i += 128) {
        int d = i / HW, hw = i - d * HW;
        float acc = 0.f;
#pragma unroll
        for (int k = 0; k < KK; k++) {
            int s = d + k - 3;
            if (s >= 0 && s < DTOT) acc += xs[s * PITCH + hw] * wl[k];
        }
        ms[d * PITCH + hw] = acc;
    }
    __syncthreads();

    // ---- softmax over hw (81) per row d: warp per row ----
    const int wid = tid >> 5, lane = tid & 31;
    for (int d = wid; d < DTOT; d += 4) {
        float* row = ms + d * PITCH;
        float m0 = row[lane];
        float m1 = row[lane + 32];
        float m2 = (lane < 17) ? row[lane + 64] : -1e30f;
        float mx = fmaxf(m0, fmaxf(m1, m2));
#pragma unroll
        for (int s = 16; s; s >>= 1) mx = fmaxf(mx, __shfl_xor_sync(~0u, mx, s));
        float e0 = __expf(m0 - mx);
        float e1 = __expf(m1 - mx);
        float e2 = (lane < 17) ? __expf(m2 - mx) : 0.f;
        float sm = e0 + e1 + e2;
#pragma unroll
        for (int s = 16; s; s >>= 1) sm += __shfl_xor_sync(~0u, sm, s);
        float inv = 1.f / sm;
        row[lane]      = e0 * inv;
        row[lane + 32] = e1 * inv;
        if (lane < 17) row[lane + 64] = e2 * inv;
        if (lane < 3)  row[HW + lane] = 0.f;   // zero pad cols
    }
    __syncthreads();

    // ---- fk[c][dd] = dot(xs[c], ms[dd]) over hw, then leaky (mask>0 => valid) ----
    for (int idx = tid; idx < CC * DTOT; idx += 128) {
        int c = idx / DTOT, dd = idx - c * DTOT;
        const float4* a = (const float4*)(xs + c * PITCH);
        const float4* b = (const float4*)(ms + dd * PITCH);
        float s = 0.f;
#pragma unroll
        for (int j = 0; j < Q4; j++) {
            float4 av = a[j], bv = b[j];
            s += av.x * bv.x + av.y * bv.y + av.z * bv.z + av.w * bv.w;
        }
        gs[idx] = (s >= 0.f) ? s : 0.01f * s;
    }
    __syncthreads();

    // ---- contrib[c][hw] = sum_dd gs[c][dd] * ms[dd][hw], 2-row register tiling ----
    float4* out4 = (float4*)(g_scr + (size_t)(n * OO + o) * CC * PITCH);
    const float4* ms4 = (const float4*)ms;
    for (int idx = tid; idx < 25 * Q4; idx += 128) {
        int pr = idx / Q4, q = idx - pr * Q4;
        int c0 = pr, c1 = pr + 25;
        bool has2 = (c1 < CC);
        const float* g0p = gs + c0 * DTOT;
        const float* g1p = gs + c1 * DTOT;
        float4 a0 = {0.f, 0.f, 0.f, 0.f};
        float4 a1 = {0.f, 0.f, 0.f, 0.f};
#pragma unroll 7
        for (int dd = 0; dd < DTOT; dd++) {
            float4 mv = ms4[dd * Q4 + q];
            float g0 = g0p[dd];
            a0.x += g0 * mv.x; a0.y += g0 * mv.y;
            a0.z += g0 * mv.z; a0.w += g0 * mv.w;
            if (has2) {
                float g1 = g1p[dd];
                a1.x += g1 * mv.x; a1.y += g1 * mv.y;
                a1.z += g1 * mv.z; a1.w += g1 * mv.w;
            }
        }
        out4[c0 * Q4 + q] = a0;
        if (has2) out4[c1 * Q4 + q] = a1;
    }
}

// one block per channel: residual + sum 24 contribs, then batchnorm over (n,hw)
__global__ __launch_bounds__(256) void k_bn(const float* __restrict__ x,
                                            const float* __restrict__ gamma,
                                            const float* __restrict__ beta,
                                            float* __restrict__ out) {
    const int c = blockIdx.x;
    const int tid = threadIdx.x;
    float v[11];
    int cnt = 0;
    float s = 0.f, s2 = 0.f;
    for (int e = tid; e < NB * HW; e += 256) {
        int n = e / HW, hw = e - n * HW;
        float val = x[(size_t)n * CC * HW + c * HW + hw];
        const float* base = g_scr + (size_t)n * OO * CC * PITCH + c * PITCH + hw;
#pragma unroll
        for (int o = 0; o < OO; o++) val += base[(size_t)o * CC * PITCH];
        v[cnt++] = val;
        s += val;
        s2 += val * val;
    }
    __shared__ float rs[256], rs2[256];
    rs[tid] = s; rs2[tid] = s2;
    __syncthreads();
    for (int st = 128; st; st >>= 1) {
        if (tid < st) { rs[tid] += rs[tid + st]; rs2[tid] += rs2[tid + st]; }
        __syncthreads();
    }
    const float invM = 1.f / (NB * HW);
    float mean = rs[0] * invM;
    float var  = rs2[0] * invM - mean * mean;
    float scale = gamma[c] * rsqrtf(var + 1e-5f);
    float shift = beta[c] - mean * scale;
    cnt = 0;
    for (int e = tid; e < NB * HW; e += 256) {
        int n = e / HW, hw = e - n * HW;
        out[(size_t)n * CC * HW + c * HW + hw] = v[cnt++] * scale + shift;
    }
}

extern "C" void kernel_launch(void* const* d_in, const int* in_sizes, int n_in,
                              void* d_out, int out_size) {
    const float* x     = (const float*)d_in[0];
    const float* w     = (const float*)d_in[1];
    // d_in[2] = conv_b: unused (constant per softmax row, cancels)
    const float* gamma = (const float*)d_in[3];
    const float* beta  = (const float*)d_in[4];
    float* out = (float*)d_out;

    k_main<<<NB * OO, 128>>>(x, w);
    k_bn<<<CC, 256>>>(x, gamma, beta, out);
}

// round 2
// speedup vs baseline: 1.4153x; 1.4153x over previous
#include <cuda_runtime.h>

#define NB   32
#define CC   49
#define HW   81
#define PITCH 84          // padded row (mult of 4), pads zeroed
#define Q4   21           // PITCH/4
#define OO   24
#define KK   7
#define DD   49
#define RP   52           // padded row count for 13x4 tiling

// scratch layout [n][c][o][PITCH] so the o-reduction reads contiguous 8KB chunks
__device__ float  g_scr[(size_t)NB * CC * OO * PITCH];   // 12.6 MB
__device__ float  g_pre[(size_t)NB * CC * HW];           // 508 KB pre-norm values
__device__ float2 g_part[CC * NB];                       // per (c,n) partial sums
__device__ float2 g_ss[CC];                              // per-c scale/shift

__global__ __launch_bounds__(128) void k_main(const float* __restrict__ x,
                                              const float* __restrict__ w) {
    const int n = blockIdx.x / OO;
    const int o = blockIdx.x % OO;
    __shared__ float xs[RP * PITCH];   // 17472 B
    __shared__ float ms[RP * PITCH];   // 17472 B
    __shared__ float gs[RP * RP];      // 10816 B  (total 45760 < 48K)
    const int tid = threadIdx.x;

    // ---- load x[n] (pitch 84), zero all pads (cols 81-83, rows 49-51) ----
    const float* xn = x + (size_t)n * CC * HW;
    for (int i = tid; i < CC * HW; i += 128) {
        int c = i / HW, hw = i - c * HW;
        xs[c * PITCH + hw] = xn[i];
    }
    for (int i = tid; i < CC * 3; i += 128) {
        int c = i / 3;
        xs[c * PITCH + HW + (i - c * 3)] = 0.f;
    }
    for (int i = tid; i < 3 * PITCH; i += 128) {
        xs[CC * PITCH + i] = 0.f;
        ms[CC * PITCH + i] = 0.f;
    }
    float wl[KK];
#pragma unroll
    for (int k = 0; k < KK; k++) wl[k] = w[o * KK + k];
    __syncthreads();

    // ---- depth conv along d (bias omitted: cancels in softmax) ----
    for (int i = tid; i < DD * HW; i += 128) {
        int d = i / HW, hw = i - d * HW;
        float acc = 0.f;
#pragma unroll
        for (int k = 0; k < KK; k++) {
            int s = d + k - 3;
            if (s >= 0) acc += xs[s * PITCH + hw] * wl[k];   // rows 49..51 are zero
        }
        ms[d * PITCH + hw] = acc;
    }
    __syncthreads();

    // ---- softmax over hw per row d: warp per row ----
    const int wid = tid >> 5, lane = tid & 31;
    for (int d = wid; d < DD; d += 4) {
        float* row = ms + d * PITCH;
        float m0 = row[lane];
        float m1 = row[lane + 32];
        float m2 = (lane < 17) ? row[lane + 64] : -1e30f;
        float mx = fmaxf(m0, fmaxf(m1, m2));
#pragma unroll
        for (int s = 16; s; s >>= 1) mx = fmaxf(mx, __shfl_xor_sync(~0u, mx, s));
        float e0 = __expf(m0 - mx);
        float e1 = __expf(m1 - mx);
        float e2 = (lane < 17) ? __expf(m2 - mx) : 0.f;
        float sm = e0 + e1 + e2;
#pragma unroll
        for (int s = 16; s; s >>= 1) sm += __shfl_xor_sync(~0u, sm, s);
        float inv = 1.f / sm;
        row[lane]      = e0 * inv;
        row[lane + 32] = e1 * inv;
        if (lane < 17) row[lane + 64] = e2 * inv;
        if (lane < 3)  row[HW + lane] = 0.f;   // zero pad cols
    }
    __syncthreads();

    // ---- fk = X * M^T, 4x4 register tile, outer product over hw ----
    // interleaved tiles: c = cg + 13*i, dd = dg + 13*j  (lane stride = 1 row -> no bank conflicts)
    for (int t = tid; t < 169; t += 128) {
        int cg = t / 13, dg = t - cg * 13;
        float a00=0,a01=0,a02=0,a03=0, a10=0,a11=0,a12=0,a13=0;
        float a20=0,a21=0,a22=0,a23=0, a30=0,a31=0,a32=0,a33=0;
        const float* xp = xs + cg * PITCH;
        const float* mp = ms + dg * PITCH;
#pragma unroll 3
        for (int hw = 0; hw < HW; hw++) {
            float x0 = xp[hw], x1 = xp[13*PITCH + hw], x2 = xp[26*PITCH + hw], x3 = xp[39*PITCH + hw];
            float b0 = mp[hw], b1 = mp[13*PITCH + hw], b2 = mp[26*PITCH + hw], b3 = mp[39*PITCH + hw];
            a00 += x0*b0; a01 += x0*b1; a02 += x0*b2; a03 += x0*b3;
            a10 += x1*b0; a11 += x1*b1; a12 += x1*b2; a13 += x1*b3;
            a20 += x2*b0; a21 += x2*b1; a22 += x2*b2; a23 += x2*b3;
            a30 += x3*b0; a31 += x3*b1; a32 += x3*b2; a33 += x3*b3;
        }
        float* g0 = gs + (cg     ) * RP + dg;
        float* g1 = gs + (cg + 13) * RP + dg;
        float* g2 = gs + (cg + 26) * RP + dg;
        float* g3 = gs + (cg + 39) * RP + dg;
        // leaky relu (mask>0 so sign(big)=sign(fk))
        g0[0]  = (a00>=0.f)?a00:0.01f*a00; g0[13] = (a01>=0.f)?a01:0.01f*a01;
        g0[26] = (a02>=0.f)?a02:0.01f*a02; g0[39] = (a03>=0.f)?a03:0.01f*a03;
        g1[0]  = (a10>=0.f)?a10:0.01f*a10; g1[13] = (a11>=0.f)?a11:0.01f*a11;
        g1[26] = (a12>=0.f)?a12:0.01f*a12; g1[39] = (a13>=0.f)?a13:0.01f*a13;
        g2[0]  = (a20>=0.f)?a20:0.01f*a20; g2[13] = (a21>=0.f)?a21:0.01f*a21;
        g2[26] = (a22>=0.f)?a22:0.01f*a22; g2[39] = (a23>=0.f)?a23:0.01f*a23;
        g3[0]  = (a30>=0.f)?a30:0.01f*a30; g3[13] = (a31>=0.f)?a31:0.01f*a31;
        g3[26] = (a32>=0.f)?a32:0.01f*a32; g3[39] = (a33>=0.f)?a33:0.01f*a33;
    }
    __syncthreads();

    // ---- contrib[c][hw] = sum_dd gs[c][dd] * ms[dd][hw], 4-row register tile ----
    float4* s4 = (float4*)g_scr;
    const float4* ms4 = (const float4*)ms;
    for (int t = tid; t < 13 * Q4; t += 128) {
        int pr = t / Q4, q = t - pr * Q4;
        int c0 = 4 * pr;
        const float* g0 = gs + (c0    ) * RP;
        const float* g1 = gs + (c0 + 1) * RP;
        const float* g2 = gs + (c0 + 2) * RP;
        const float* g3 = gs + (c0 + 3) * RP;   // rows >=49 are zeros (leaky(0))
        float4 A0 = {0,0,0,0}, A1 = A0, A2 = A0, A3 = A0;
#pragma unroll 7
        for (int dd = 0; dd < DD; dd++) {
            float4 mv = ms4[dd * Q4 + q];
            float v0 = g0[dd], v1 = g1[dd], v2 = g2[dd], v3 = g3[dd];
            A0.x += v0*mv.x; A0.y += v0*mv.y; A0.z += v0*mv.z; A0.w += v0*mv.w;
            A1.x += v1*mv.x; A1.y += v1*mv.y; A1.z += v1*mv.z; A1.w += v1*mv.w;
            A2.x += v2*mv.x; A2.y += v2*mv.y; A2.z += v2*mv.z; A2.w += v2*mv.w;
            A3.x += v3*mv.x; A3.y += v3*mv.y; A3.z += v3*mv.z; A3.w += v3*mv.w;
        }
        size_t base = ((size_t)(n * CC + c0) * OO + o) * Q4 + q;
        s4[base] = A0;
        if (c0 + 1 < CC) s4[base + (size_t)OO * Q4]     = A1;
        if (c0 + 2 < CC) s4[base + (size_t)2 * OO * Q4] = A2;
        if (c0 + 3 < CC) s4[base + (size_t)3 * OO * Q4] = A3;
    }
}

// per-(n,c): residual + sum over o, write pre-norm values + partial stats
__global__ __launch_bounds__(96) void k_sum(const float* __restrict__ x) {
    const int nc = blockIdx.x;              // n*CC + c
    const int t = threadIdx.x;
    float val = 0.f;
    if (t < HW) {
        val = x[(size_t)nc * HW + t];
        const float* base = g_scr + (size_t)nc * OO * PITCH + t;
#pragma unroll
        for (int o = 0; o < OO; o++) val += base[o * PITCH];
        g_pre[(size_t)nc * HW + t] = val;
    }
    float s  = (t < HW) ? val       : 0.f;
    float s2 = (t < HW) ? val * val : 0.f;
#pragma unroll
    for (int sh = 16; sh; sh >>= 1) {
        s  += __shfl_xor_sync(~0u, s,  sh);
        s2 += __shfl_xor_sync(~0u, s2, sh);
    }
    __shared__ float ws[3], ws2[3];
    int wid = t >> 5, lane = t & 31;
    if (lane == 0) { ws[wid] = s; ws2[wid] = s2; }
    __syncthreads();
    if (t == 0) {
        int n = nc / CC, c = nc - n * CC;
        g_part[c * NB + n] = make_float2(ws[0] + ws[1] + ws[2],
                                         ws2[0] + ws2[1] + ws2[2]);
    }
}

__global__ void k_stats(const float* __restrict__ gamma,
                        const float* __restrict__ beta) {
    const int c = blockIdx.x, lane = threadIdx.x;
    float2 p = g_part[c * NB + lane];
    float s = p.x, s2 = p.y;
#pragma unroll
    for (int sh = 16; sh; sh >>= 1) {
        s  += __shfl_xor_sync(~0u, s,  sh);
        s2 += __shfl_xor_sync(~0u, s2, sh);
    }
    if (lane == 0) {
        const float invM = 1.f / (NB * HW);
        float mean = s * invM;
        float var  = s2 * invM - mean * mean;
        float sc = gamma[c] * rsqrtf(var + 1e-5f);
        g_ss[c] = make_float2(sc, beta[c] - mean * sc);
    }
}

__global__ __launch_bounds__(256) void k_norm(float* __restrict__ out) {
    int i = blockIdx.x * 256 + threadIdx.x;
    if (i < NB * CC * HW) {
        int c = (i / HW) % CC;
        float2 ss = g_ss[c];
        out[i] = g_pre[i] * ss.x + ss.y;
    }
}

extern "C" void kernel_launch(void* const* d_in, const int* in_sizes, int n_in,
                              void* d_out, int out_size) {
    const float* x     = (const float*)d_in[0];
    const float* w     = (const float*)d_in[1];
    // d_in[2] = conv_b: unused (constant per softmax row, cancels)
    const float* gamma = (const float*)d_in[3];
    const float* beta  = (const float*)d_in[4];
    float* out = (float*)d_out;

    k_main<<<NB * OO, 128>>>(x, w);
    k_sum<<<NB * CC, 96>>>(x);
    k_stats<<<CC, 32>>>(gamma, beta);
    k_norm<<<(NB * CC * HW + 255) / 256, 256>>>(out);
}

// round 3
// speedup vs baseline: 1.6396x; 1.1585x over previous
#include <cuda_runtime.h>

#define NB   32
#define CC   49
#define HW   81
#define PITCH 84          // padded row (mult of 4), pads zeroed
#define Q4   21           // PITCH/4
#define OO   24
#define KK   7
#define DD   49
#define GP   56           // gs row pitch (c-dim, padded, mult of 4)

// scratch layout [n][c][o][PITCH] so the o-reduction reads contiguous chunks
__device__ float  g_scr[(size_t)NB * CC * OO * PITCH];   // 12.6 MB
__device__ float  g_pre[(size_t)NB * CC * PITCH];        // 527 KB pre-norm (pitched)
__device__ float2 g_part[CC * NB];                       // per (c,n) partial sums

typedef unsigned long long ull;

__device__ __forceinline__ void ffma2(ull& d, ull a, ull b) {
    asm("fma.rn.f32x2 %0, %1, %2, %0;" : "+l"(d) : "l"(a), "l"(b));
}
__device__ __forceinline__ ull pack2(float x) {
    ull r;
    unsigned u = __float_as_uint(x);
    asm("mov.b64 %0, {%1, %1};" : "=l"(r) : "r"(u));
    return r;
}
__device__ __forceinline__ float hadd2(ull v) {
    float2 f = *(float2*)&v;
    return f.x + f.y;
}

__global__ __launch_bounds__(128) void k_main(const float* __restrict__ x,
                                              const float* __restrict__ w) {
    const int n = blockIdx.x / OO;
    const int o = blockIdx.x % OO;
    __shared__ __align__(16) float xs[52 * PITCH];   // 17472 B
    __shared__ __align__(16) float ms[52 * PITCH];   // 17472 B
    __shared__ __align__(16) float gs[DD * GP];      // 10976 B  (dd-major) => 45920 total
    const int tid = threadIdx.x;

    // ---- load x[n] (pitch 84), zero pads (cols 81-83, rows 49-51 of xs & ms) ----
    const float* xn = x + (size_t)n * CC * HW;
    for (int i = tid; i < CC * HW; i += 128) {
        int c = i / HW, hw = i - c * HW;
        xs[c * PITCH + hw] = xn[i];
    }
    for (int i = tid; i < CC * 3; i += 128) {
        int c = i / 3;
        xs[c * PITCH + HW + (i - c * 3)] = 0.f;
    }
    for (int i = tid; i < 3 * PITCH; i += 128) {
        xs[CC * PITCH + i] = 0.f;
        ms[CC * PITCH + i] = 0.f;
    }
    ull wl2[KK];
#pragma unroll
    for (int k = 0; k < KK; k++) wl2[k] = pack2(w[o * KK + k]);
    __syncthreads();

    // ---- depth conv along d, f32x2 over hw pairs (bias cancels in softmax) ----
    for (int i = tid; i < DD * 42; i += 128) {
        int d = i / 42, p = i - d * 42;
        ull acc = 0ull;
#pragma unroll
        for (int k = 0; k < KK; k++) {
            int s = d + k - 3;
            if (s >= 0) {   // rows 49..51 exist and are zero
                ull xv = *(const ull*)(xs + s * PITCH + 2 * p);
                ffma2(acc, wl2[k], xv);
            }
        }
        *(ull*)(ms + d * PITCH + 2 * p) = acc;
    }
    __syncthreads();

    // ---- softmax over hw per row d: warp per row ----
    const int wid = tid >> 5, lane = tid & 31;
    for (int d = wid; d < DD; d += 4) {
        float* row = ms + d * PITCH;
        float m0 = row[lane];
        float m1 = row[lane + 32];
        float m2 = (lane < 17) ? row[lane + 64] : -1e30f;
        float mx = fmaxf(m0, fmaxf(m1, m2));
#pragma unroll
        for (int s = 16; s; s >>= 1) mx = fmaxf(mx, __shfl_xor_sync(~0u, mx, s));
        float e0 = __expf(m0 - mx);
        float e1 = __expf(m1 - mx);
        float e2 = (lane < 17) ? __expf(m2 - mx) : 0.f;
        float sm = e0 + e1 + e2;
#pragma unroll
        for (int s = 16; s; s >>= 1) sm += __shfl_xor_sync(~0u, sm, s);
        float inv = 1.f / sm;
        row[lane]      = e0 * inv;
        row[lane + 32] = e1 * inv;
        if (lane < 17) row[lane + 64] = e2 * inv;
        if (lane < 3)  row[HW + lane] = 0.f;   // keep pad cols zero
    }
    __syncthreads();

    // ---- fk = X * M^T, 4x4 register tile, f32x2 over hw; result -> gs[dd][c] ----
#pragma unroll 1
    for (int t = tid; t < 169; t += 128) {
        int cg = t / 13, dg = t - cg * 13;
        ull a[4][4];
#pragma unroll
        for (int i = 0; i < 4; i++)
#pragma unroll
            for (int j = 0; j < 4; j++) a[i][j] = 0ull;
        const float* xp = xs + cg * PITCH;
        const float* mp = ms + dg * PITCH;
#pragma unroll 6
        for (int p = 0; p < 42; p++) {
            ull x0 = *(const ull*)(xp + 2 * p);
            ull x1 = *(const ull*)(xp + 13 * PITCH + 2 * p);
            ull x2 = *(const ull*)(xp + 26 * PITCH + 2 * p);
            ull x3 = *(const ull*)(xp + 39 * PITCH + 2 * p);
            ull b0 = *(const ull*)(mp + 2 * p);
            ull b1 = *(const ull*)(mp + 13 * PITCH + 2 * p);
            ull b2 = *(const ull*)(mp + 26 * PITCH + 2 * p);
            ull b3 = *(const ull*)(mp + 39 * PITCH + 2 * p);
            ffma2(a[0][0], x0, b0); ffma2(a[0][1], x0, b1); ffma2(a[0][2], x0, b2); ffma2(a[0][3], x0, b3);
            ffma2(a[1][0], x1, b0); ffma2(a[1][1], x1, b1); ffma2(a[1][2], x1, b2); ffma2(a[1][3], x1, b3);
            ffma2(a[2][0], x2, b0); ffma2(a[2][1], x2, b1); ffma2(a[2][2], x2, b2); ffma2(a[2][3], x2, b3);
            ffma2(a[3][0], x3, b0); ffma2(a[3][1], x3, b1); ffma2(a[3][2], x3, b2); ffma2(a[3][3], x3, b3);
        }
#pragma unroll
        for (int j = 0; j < 4; j++) {
            int dd = dg + 13 * j;
            if (dd < DD) {
#pragma unroll
                for (int i = 0; i < 4; i++) {
                    float s = hadd2(a[i][j]);
                    s = (s >= 0.f) ? s : 0.01f * s;   // leaky (mask>0 => sign preserved)
                    gs[dd * GP + cg + 13 * i] = s;
                }
            }
        }
    }
    __syncthreads();

    // ---- contrib[c][hw] = sum_dd gs[dd][c] * ms[dd][hw]; 4c x 12hw tile, f32x2 ----
    if (tid < 91) {
        int pr = tid / 7, qg = tid - pr * 7;   // pr: 13 c-groups of 4, qg: 7 hw-chunks of 12
        int c0 = 4 * pr;
        ull A[4][6];
#pragma unroll
        for (int i = 0; i < 4; i++)
#pragma unroll
            for (int k = 0; k < 6; k++) A[i][k] = 0ull;
#pragma unroll 7
        for (int dd = 0; dd < DD; dd++) {
            float4 g4 = *(const float4*)(gs + dd * GP + c0);
            ull p0 = pack2(g4.x), p1 = pack2(g4.y), p2 = pack2(g4.z), p3 = pack2(g4.w);
            const float* mrow = ms + dd * PITCH + qg * 12;
            ulonglong2 v0 = *(const ulonglong2*)(mrow);
            ulonglong2 v1 = *(const ulonglong2*)(mrow + 4);
            ulonglong2 v2 = *(const ulonglong2*)(mrow + 8);
            ffma2(A[0][0], p0, v0.x); ffma2(A[0][1], p0, v0.y); ffma2(A[0][2], p0, v1.x);
            ffma2(A[0][3], p0, v1.y); ffma2(A[0][4], p0, v2.x); ffma2(A[0][5], p0, v2.y);
            ffma2(A[1][0], p1, v0.x); ffma2(A[1][1], p1, v0.y); ffma2(A[1][2], p1, v1.x);
            ffma2(A[1][3], p1, v1.y); ffma2(A[1][4], p1, v2.x); ffma2(A[1][5], p1, v2.y);
            ffma2(A[2][0], p2, v0.x); ffma2(A[2][1], p2, v0.y); ffma2(A[2][2], p2, v1.x);
            ffma2(A[2][3], p2, v1.y); ffma2(A[2][4], p2, v2.x); ffma2(A[2][5], p2, v2.y);
            ffma2(A[3][0], p3, v0.x); ffma2(A[3][1], p3, v0.y); ffma2(A[3][2], p3, v1.x);
            ffma2(A[3][3], p3, v1.y); ffma2(A[3][4], p3, v2.x); ffma2(A[3][5], p3, v2.y);
        }
#pragma unroll
        for (int i = 0; i < 4; i++) {
            int c = c0 + i;
            if (c < CC) {
                float* dst = g_scr + ((size_t)(n * CC + c) * OO + o) * PITCH + qg * 12;
                ulonglong2 w0 = {A[i][0], A[i][1]};
                ulonglong2 w1 = {A[i][2], A[i][3]};
                ulonglong2 w2 = {A[i][4], A[i][5]};
                *(ulonglong2*)(dst)     = w0;
                *(ulonglong2*)(dst + 4) = w1;
                *(ulonglong2*)(dst + 8) = w2;
            }
        }
    }
}

// per-(n,c): residual + sum over o (float4, 24-deep MLP), partial stats
__global__ __launch_bounds__(32) void k_sum(const float* __restrict__ x) {
    const int nc = blockIdx.x;              // n*CC + c
    const int q = threadIdx.x;              // 0..31, 21 active float4 columns
    float4 v = {0.f, 0.f, 0.f, 0.f};
    if (q < Q4) {
        const float4* base = (const float4*)g_scr + ((size_t)nc * OO) * Q4 + q;
#pragma unroll
        for (int o = 0; o < OO; o++) {
            float4 t = base[o * Q4];
            v.x += t.x; v.y += t.y; v.z += t.z; v.w += t.w;
        }
        // residual (x packed to 81, scalar guarded loads; pads stay 0)
        const float* xr = x + (size_t)nc * HW + 4 * q;
        int rem = HW - 4 * q;
        if (rem > 0) v.x += xr[0];
        if (rem > 1) v.y += xr[1];
        if (rem > 2) v.z += xr[2];
        if (rem > 3) v.w += xr[3];
        ((float4*)g_pre)[(size_t)nc * Q4 + q] = v;
    }
    float s  = v.x + v.y + v.z + v.w;
    float s2 = v.x * v.x + v.y * v.y + v.z * v.z + v.w * v.w;
#pragma unroll
    for (int sh = 16; sh; sh >>= 1) {
        s  += __shfl_xor_sync(~0u, s,  sh);
        s2 += __shfl_xor_sync(~0u, s2, sh);
    }
    if (q == 0) {
        int n = nc / CC, c = nc - n * CC;
        g_part[c * NB + n] = make_float2(s, s2);
    }
}

// block per channel: reduce partials -> scale/shift, then normalize
__global__ __launch_bounds__(256) void k_norm(const float* __restrict__ gamma,
                                              const float* __restrict__ beta,
                                              float* __restrict__ out) {
    const int c = blockIdx.x;
    const int tid = threadIdx.x;
    __shared__ float2 ss;
    if (tid < 32) {
        float2 p = g_part[c * NB + tid];
        float s = p.x, s2 = p.y;
#pragma unroll
        for (int sh = 16; sh; sh >>= 1) {
            s  += __shfl_xor_sync(~0u, s,  sh);
            s2 += __shfl_xor_sync(~0u, s2, sh);
        }
        if (tid == 0) {
            const float invM = 1.f / (NB * HW);
            float mean = s * invM;
            float var  = s2 * invM - mean * mean;
            float sc = gamma[c] * rsqrtf(var + 1e-5f);
            ss = make_float2(sc, beta[c] - mean * sc);
        }
    }
    __syncthreads();
    float2 f = ss;
    for (int i = tid; i < NB * HW; i += 256) {
        int n = i / HW, hw = i - n * HW;
        float v = g_pre[(size_t)(n * CC + c) * PITCH + hw];
        out[(size_t)(n * CC + c) * HW + hw] = v * f.x + f.y;
    }
}

extern "C" void kernel_launch(void* const* d_in, const int* in_sizes, int n_in,
                              void* d_out, int out_size) {
    const float* x     = (const float*)d_in[0];
    const float* w     = (const float*)d_in[1];
    // d_in[2] = conv_b: unused (constant per softmax row, cancels)
    const float* gamma = (const float*)d_in[3];
    const float* beta  = (const float*)d_in[4];
    float* out = (float*)d_out;

    k_main<<<NB * OO, 128>>>(x, w);
    k_sum<<<NB * CC, 32>>>(x);
    k_norm<<<CC, 256>>>(gamma, beta, out);
}

// round 4
// speedup vs baseline: 1.6985x; 1.0359x over previous
#include <cuda_runtime.h>

#define NB   32
#define CC   49
#define HW   81
#define PITCH 84          // padded row floats (mult of 4)
#define Q4   21           // PITCH/4
#define OO   24
#define KK   7
#define DD   49
#define RP   56           // padded row count (conv window + fk dd overreach)
#define GP   56           // gs row pitch (c-dim)

// scratch layout [n][c][o][PITCH] so the o-reduction reads contiguous chunks
__device__ float  g_scr[(size_t)NB * CC * OO * PITCH];   // 12.6 MB
__device__ float  g_pre[(size_t)NB * CC * PITCH];        // 527 KB pre-norm (pitched)
__device__ float2 g_part[CC * NB];                       // per (c,n) partial sums

typedef unsigned long long ull;

__device__ __forceinline__ void ffma2(ull& d, ull a, ull b) {
    asm("fma.rn.f32x2 %0, %1, %2, %0;" : "+l"(d) : "l"(a), "l"(b));
}
__device__ __forceinline__ ull pack2(float x) {
    ull r;
    unsigned u = __float_as_uint(x);
    asm("mov.b64 %0, {%1, %1};" : "=l"(r) : "r"(u));
    return r;
}
__device__ __forceinline__ float hadd2(ull v) {
    float2 f = *(float2*)&v;
    return f.x + f.y;
}

__global__ __launch_bounds__(128, 5) void k_main(const float* __restrict__ x,
                                                 const float* __restrict__ w) {
    const int n = blockIdx.x / OO;
    const int o = blockIdx.x % OO;
    // xa: holds xs during load/conv/fk; after fk's register accumulation it is
    // reused (behind a barrier) as gs[dd][c] (54*GP floats = 12096B <= 18816B).
    __shared__ __align__(16) float xa[RP * PITCH];   // 18816 B
    __shared__ __align__(16) float ms[RP * PITCH];   // 18816 B   (total 36.75KB)
    float* const xs = xa;
    float* const gs = xa;
    const int tid = threadIdx.x;

    // ---- load x[n] (pitch 84); zero pad cols 81-83 and rows 49-55 ----
    const float* xn = x + (size_t)n * CC * HW;
    for (int i = tid; i < CC * HW; i += 128) {
        int c = i / HW, hw = i - c * HW;
        xs[c * PITCH + hw] = xn[i];
    }
    for (int i = tid; i < CC * 3; i += 128) {
        int c = i / 3;
        xs[c * PITCH + HW + (i - c * 3)] = 0.f;
    }
    for (int i = tid; i < 7 * PITCH; i += 128) {
        xs[CC * PITCH + i] = 0.f;
        ms[CC * PITCH + i] = 0.f;
    }
    ull wl2[KK];
#pragma unroll
    for (int k = 0; k < KK; k++) wl2[k] = pack2(w[o * KK + k]);
    __syncthreads();

    // ---- depth conv along d: sliding window in regs, 1 load per output ----
    // 126 threads: (hw-pair p, d-segment seg); bias cancels in softmax.
    if (tid < 126) {
        int seg = tid / 42;
        int p = tid - seg * 42;
        int d0 = seg * 17;
        int dlen = (seg == 2) ? 15 : 17;
        ull win[KK];
#pragma unroll
        for (int k = 0; k < KK; k++) {
            int r = d0 - 3 + k;
            win[k] = (r >= 0) ? *(const ull*)(xs + r * PITCH + 2 * p) : 0ull;
        }
        for (int d = d0; d < d0 + dlen; d++) {
            ull acc = 0ull;
#pragma unroll
            for (int k = 0; k < KK; k++) ffma2(acc, wl2[k], win[k]);
            *(ull*)(ms + d * PITCH + 2 * p) = acc;
#pragma unroll
            for (int k = 0; k < KK - 1; k++) win[k] = win[k + 1];
            win[6] = *(const ull*)(xs + (d + 4) * PITCH + 2 * p);  // row <= 52, zeroed
        }
    }
    __syncthreads();

    // ---- softmax over hw per row d: warp per row ----
    const int wid = tid >> 5, lane = tid & 31;
    for (int d = wid; d < DD; d += 4) {
        float* row = ms + d * PITCH;
        float m0 = row[lane];
        float m1 = row[lane + 32];
        float m2 = (lane < 17) ? row[lane + 64] : -1e30f;
        float mx = fmaxf(m0, fmaxf(m1, m2));
#pragma unroll
        for (int s = 16; s; s >>= 1) mx = fmaxf(mx, __shfl_xor_sync(~0u, mx, s));
        float e0 = __expf(m0 - mx);
        float e1 = __expf(m1 - mx);
        float e2 = (lane < 17) ? __expf(m2 - mx) : 0.f;
        float sm = e0 + e1 + e2;
#pragma unroll
        for (int s = 16; s; s >>= 1) sm += __shfl_xor_sync(~0u, sm, s);
        float inv = 1.f / sm;
        row[lane]      = e0 * inv;
        row[lane + 32] = e1 * inv;
        if (lane < 17) row[lane + 64] = e2 * inv;
        if (lane < 3)  row[HW + lane] = 0.f;   // keep pad cols zero
    }
    __syncthreads();

    // ---- fk = X * M^T, single pass: 117 tiles of 4c x 6dd, f32x2 over hw ----
    // c = cg + 13*i (i<4, c<=51: rows 49-51 zero -> gs=0, harmless)
    // dd = ddg + 9*j (j<6, dd<=53: ms rows 49-55 zero -> gs=0, never read)
    ull a[4][6];
    int cg = 0, dg = 0;
    if (tid < 117) {
        cg = tid / 9; dg = tid - cg * 9;
#pragma unroll
        for (int i = 0; i < 4; i++)
#pragma unroll
            for (int j = 0; j < 6; j++) a[i][j] = 0ull;
        const float* xp = xs + cg * 13 * 0 + cg * PITCH;   // row cg
        const float* mp = ms + dg * PITCH;
#pragma unroll 6
        for (int p = 0; p < 42; p++) {
            ull x0 = *(const ull*)(xp + 2 * p);
            ull x1 = *(const ull*)(xp + 13 * PITCH + 2 * p);
            ull x2 = *(const ull*)(xp + 26 * PITCH + 2 * p);
            ull x3 = *(const ull*)(xp + 39 * PITCH + 2 * p);
            ull b0 = *(const ull*)(mp + 2 * p);
            ull b1 = *(const ull*)(mp +  9 * PITCH + 2 * p);
            ull b2 = *(const ull*)(mp + 18 * PITCH + 2 * p);
            ull b3 = *(const ull*)(mp + 27 * PITCH + 2 * p);
            ull b4 = *(const ull*)(mp + 36 * PITCH + 2 * p);
            ull b5 = *(const ull*)(mp + 45 * PITCH + 2 * p);
            ffma2(a[0][0], x0, b0); ffma2(a[0][1], x0, b1); ffma2(a[0][2], x0, b2);
            ffma2(a[0][3], x0, b3); ffma2(a[0][4], x0, b4); ffma2(a[0][5], x0, b5);
            ffma2(a[1][0], x1, b0); ffma2(a[1][1], x1, b1); ffma2(a[1][2], x1, b2);
            ffma2(a[1][3], x1, b3); ffma2(a[1][4], x1, b4); ffma2(a[1][5], x1, b5);
            ffma2(a[2][0], x2, b0); ffma2(a[2][1], x2, b1); ffma2(a[2][2], x2, b2);
            ffma2(a[2][3], x2, b3); ffma2(a[2][4], x2, b4); ffma2(a[2][5], x2, b5);
            ffma2(a[3][0], x3, b0); ffma2(a[3][1], x3, b1); ffma2(a[3][2], x3, b2);
            ffma2(a[3][3], x3, b3); ffma2(a[3][4], x3, b4); ffma2(a[3][5], x3, b5);
        }
    }
    __syncthreads();           // all xs reads done -> xa becomes gs
    if (tid < 117) {
#pragma unroll
        for (int j = 0; j < 6; j++) {
            int dd = dg + 9 * j;
#pragma unroll
            for (int i = 0; i < 4; i++) {
                float s = hadd2(a[i][j]);
                s = (s >= 0.f) ? s : 0.01f * s;   // leaky (mask>0 => sign preserved)
                gs[dd * GP + cg + 13 * i] = s;
            }
        }
    }
    __syncthreads();

    // ---- contrib[c][hw] = sum_dd gs[dd][c] * ms[dd][hw]; 4c x 12hw, f32x2 ----
    if (tid < 91) {
        int pr = tid / 7, qg = tid - pr * 7;
        int c0 = 4 * pr;
        ull A[4][6];
#pragma unroll
        for (int i = 0; i < 4; i++)
#pragma unroll
            for (int k = 0; k < 6; k++) A[i][k] = 0ull;
#pragma unroll 7
        for (int dd = 0; dd < DD; dd++) {
            float4 g4 = *(const float4*)(gs + dd * GP + c0);
            ull p0 = pack2(g4.x), p1 = pack2(g4.y), p2 = pack2(g4.z), p3 = pack2(g4.w);
            const float* mrow = ms + dd * PITCH + qg * 12;
            ulonglong2 v0 = *(const ulonglong2*)(mrow);
            ulonglong2 v1 = *(const ulonglong2*)(mrow + 4);
            ulonglong2 v2 = *(const ulonglong2*)(mrow + 8);
            ffma2(A[0][0], p0, v0.x); ffma2(A[0][1], p0, v0.y); ffma2(A[0][2], p0, v1.x);
            ffma2(A[0][3], p0, v1.y); ffma2(A[0][4], p0, v2.x); ffma2(A[0][5], p0, v2.y);
            ffma2(A[1][0], p1, v0.x); ffma2(A[1][1], p1, v0.y); ffma2(A[1][2], p1, v1.x);
            ffma2(A[1][3], p1, v1.y); ffma2(A[1][4], p1, v2.x); ffma2(A[1][5], p1, v2.y);
            ffma2(A[2][0], p2, v0.x); ffma2(A[2][1], p2, v0.y); ffma2(A[2][2], p2, v1.x);
            ffma2(A[2][3], p2, v1.y); ffma2(A[2][4], p2, v2.x); ffma2(A[2][5], p2, v2.y);
            ffma2(A[3][0], p3, v0.x); ffma2(A[3][1], p3, v0.y); ffma2(A[3][2], p3, v1.x);
            ffma2(A[3][3], p3, v1.y); ffma2(A[3][4], p3, v2.x); ffma2(A[3][5], p3, v2.y);
        }
#pragma unroll
        for (int i = 0; i < 4; i++) {
            int c = c0 + i;
            if (c < CC) {
                float* dst = g_scr + ((size_t)(n * CC + c) * OO + o) * PITCH + qg * 12;
                ulonglong2 w0 = {A[i][0], A[i][1]};
                ulonglong2 w1 = {A[i][2], A[i][3]};
                ulonglong2 w2 = {A[i][4], A[i][5]};
                *(ulonglong2*)(dst)     = w0;
                *(ulonglong2*)(dst + 4) = w1;
                *(ulonglong2*)(dst + 8) = w2;
            }
        }
    }
}

// per-(n,c): residual + sum over o (float4, 24-deep MLP), partial stats
__global__ __launch_bounds__(32) void k_sum(const float* __restrict__ x) {
    const int nc = blockIdx.x;              // n*CC + c
    const int q = threadIdx.x;              // 0..31, 21 active float4 columns
    float4 v = {0.f, 0.f, 0.f, 0.f};
    if (q < Q4) {
        const float4* base = (const float4*)g_scr + ((size_t)nc * OO) * Q4 + q;
#pragma unroll
        for (int o = 0; o < OO; o++) {
            float4 t = base[o * Q4];
            v.x += t.x; v.y += t.y; v.z += t.z; v.w += t.w;
        }
        const float* xr = x + (size_t)nc * HW + 4 * q;
        int rem = HW - 4 * q;
        if (rem > 0) v.x += xr[0];
        if (rem > 1) v.y += xr[1];
        if (rem > 2) v.z += xr[2];
        if (rem > 3) v.w += xr[3];
        ((float4*)g_pre)[(size_t)nc * Q4 + q] = v;
    }
    float s  = v.x + v.y + v.z + v.w;
    float s2 = v.x * v.x + v.y * v.y + v.z * v.z + v.w * v.w;
#pragma unroll
    for (int sh = 16; sh; sh >>= 1) {
        s  += __shfl_xor_sync(~0u, s,  sh);
        s2 += __shfl_xor_sync(~0u, s2, sh);
    }
    if (q == 0) {
        int n = nc / CC, c = nc - n * CC;
        g_part[c * NB + n] = make_float2(s, s2);
    }
}

// block per channel: reduce partials -> scale/shift, then normalize
__global__ __launch_bounds__(256) void k_norm(const float* __restrict__ gamma,
                                              const float* __restrict__ beta,
                                              float* __restrict__ out) {
    const int c = blockIdx.x;
    const int tid = threadIdx.x;
    __shared__ float2 ss;
    if (tid < 32) {
        float2 p = g_part[c * NB + tid];
        float s = p.x, s2 = p.y;
#pragma unroll
        for (int sh = 16; sh; sh >>= 1) {
            s  += __shfl_xor_sync(~0u, s,  sh);
            s2 += __shfl_xor_sync(~0u, s2, sh);
        }
        if (tid == 0) {
            const float invM = 1.f / (NB * HW);
            float mean = s * invM;
            float var  = s2 * invM - mean * mean;
            float sc = gamma[c] * rsqrtf(var + 1e-5f);
            ss = make_float2(sc, beta[c] - mean * sc);
        }
    }
    __syncthreads();
    float2 f = ss;
    for (int i = tid; i < NB * HW; i += 256) {
        int n = i / HW, hw = i - n * HW;
        float v = g_pre[(size_t)(n * CC + c) * PITCH + hw];
        out[(size_t)(n * CC + c) * HW + hw] = v * f.x + f.y;
    }
}

extern "C" void kernel_launch(void* const* d_in, const int* in_sizes, int n_in,
                              void* d_out, int out_size) {
    const float* x     = (const float*)d_in[0];
    const float* w     = (const float*)d_in[1];
    // d_in[2] = conv_b: unused (constant per softmax row, cancels)
    const float* gamma = (const float*)d_in[3];
    const float* beta  = (const float*)d_in[4];
    float* out = (float*)d_out;

    k_main<<<NB * OO, 128>>>(x, w);
    k_sum<<<NB * CC, 32>>>(x);
    k_norm<<<CC, 256>>>(gamma, beta, out);
}